// round 2
// baseline (speedup 1.0000x reference)
#include <cuda_runtime.h>
#include <math.h>

#define NN 8192
#define EE 262144
#define CC 64
#define NMASK (NN - 1)

// ---- static device scratch (zero-initialized at module load) ----
__device__ int   g_map[(size_t)NN * NN];   // last-write-wins map: stores e+1, reset each launch
__device__ float g_waw[EE];                // winner? gated weight : -1
__device__ int   g_rowcnt[NN];
__device__ int   g_rowptr[NN + 1];
__device__ int   g_rowfill[NN];
__device__ float g_deg[NN];
__device__ float g_dinv[NN];
__device__ int   g_csr_col[EE];
__device__ float g_csr_w[EE];
__device__ float g_z[NN * CC];
__device__ float g_tx1[NN * CC];
__device__ float g_tx2[NN * CC];
__device__ float g_sig;

// ---- K0: per-launch init ----
__global__ void k_init(const float* __restrict__ adaptive) {
    int i = blockIdx.x * blockDim.x + threadIdx.x;
    if (i < NN) {
        g_deg[i] = 1.0f;       // identity contribution to degree
        g_rowcnt[i] = 0;
        g_rowfill[i] = 0;
    }
    if (i == 0) g_sig = 1.0f / (1.0f + expf(-adaptive[0]));
}

// ---- K1: mark max edge index per (row,col) ----
__global__ void k_pass1(const int* __restrict__ ei) {
    int e = blockIdx.x * blockDim.x + threadIdx.x;
    if (e >= EE) return;
    int r = ei[e] & NMASK;
    int c = ei[EE + e] & NMASK;
    atomicMax(&g_map[r * NN + c], e + 1);
}

// ---- K2: decide winners, accumulate degree + row histogram ----
__global__ void k_pass2(const int* __restrict__ ei,
                        const float* __restrict__ ew) {
    int e = blockIdx.x * blockDim.x + threadIdx.x;
    if (e >= EE) return;
    int r = ei[e] & NMASK;
    int c = ei[EE + e] & NMASK;
    int key = r * NN + c;
    bool win = (g_map[key] == e + 1);
    if (win) {
        float aw = ew[e] * g_sig;
        g_waw[e] = aw;
        atomicAdd(&g_rowcnt[r], 1);
        atomicAdd(&g_deg[r], aw);
    } else {
        g_waw[e] = -1.0f;
    }
}

// ---- K3: exclusive scan of rowcnt -> rowptr, and dinv = deg^-1/2 ----
__global__ void k_scan() {
    __shared__ int s[1024];
    int t = threadIdx.x;          // 1024 threads, 8 rows each
    int base = t * 8;
    int local[8];
    int sum = 0;
#pragma unroll
    for (int j = 0; j < 8; j++) { local[j] = sum; sum += g_rowcnt[base + j]; }
    s[t] = sum;
    __syncthreads();
    for (int off = 1; off < 1024; off <<= 1) {
        int v = (t >= off) ? s[t - off] : 0;
        __syncthreads();
        s[t] += v;
        __syncthreads();
    }
    int excl = (t == 0) ? 0 : s[t - 1];
#pragma unroll
    for (int j = 0; j < 8; j++) g_rowptr[base + j] = excl + local[j];
    if (t == 1023) g_rowptr[NN] = s[1023];
    for (int i = t; i < NN; i += 1024) g_dinv[i] = rsqrtf(g_deg[i]);
}

// ---- K4: scatter winners into CSR; reset map (self-cleaning) ----
__global__ void k_pass3(const int* __restrict__ ei) {
    int e = blockIdx.x * blockDim.x + threadIdx.x;
    if (e >= EE) return;
    int r = ei[e] & NMASK;
    int c = ei[EE + e] & NMASK;
    float aw = g_waw[e];
    if (aw >= 0.0f) {
        int pos = atomicAdd(&g_rowfill[r], 1);
        int slot = g_rowptr[r] + pos;
        g_csr_col[slot] = c;
        g_csr_w[slot] = aw;
    }
    g_map[r * NN + c] = 0;   // losers+winner all write 0: idempotent
}

// ---- K5: z = dinv .* xin ----
__global__ void k_scale(const float* __restrict__ xin) {
    int i = blockIdx.x * blockDim.x + threadIdx.x;
    if (i < NN * CC) g_z[i] = g_dinv[i >> 6] * xin[i];
}

// ---- K6: out = alpha * (L @ xin) + beta * other ----
// (L x)[i] = xin[i] - dinv[i] * ( z[i] + sum_edges aw * z[col] )
__global__ void k_spmm(const float* __restrict__ xin,
                       const float* __restrict__ other,
                       float* __restrict__ out,
                       float alpha, float beta) {
    int row = blockIdx.x * blockDim.y + threadIdx.y;
    int t = threadIdx.x;               // channel 0..63
    if (row >= NN) return;
    float acc = g_z[row * CC + t];     // identity term
    int s = g_rowptr[row];
    int eend = g_rowptr[row + 1];
    float di = g_dinv[row];
    for (int k = s; k < eend; k++) {
        int col  = __ldg(&g_csr_col[k]);
        float w  = __ldg(&g_csr_w[k]);
        acc += w * g_z[col * CC + t];
    }
    float y = xin[row * CC + t] - di * acc;
    out[row * CC + t] = alpha * y + beta * other[row * CC + t];
}

// ---- K7: out = Tx0@W0 + Tx1@W1 + Tx2@W2 + bias ----
// W layout: (3, 64, 64) row-major. Block: 64 outc x 4 rows, 32 rows/block.
__global__ void k_gemm(const float* __restrict__ x,
                       const float* __restrict__ W,
                       const float* __restrict__ bias,
                       float* __restrict__ out) {
    __shared__ float sW[3 * CC * CC];  // 48 KB
    int tid = threadIdx.y * 64 + threadIdx.x;
    for (int i = tid; i < 3 * CC * CC; i += 256) sW[i] = W[i];
    __syncthreads();
    int o = threadIdx.x;
    int rbase = blockIdx.x * 32;
    float b = bias[o];
    for (int r = rbase + threadIdx.y; r < rbase + 32; r += 4) {
        float acc = b;
        const float* x0 = x      + r * CC;
        const float* x1 = g_tx1  + r * CC;
        const float* x2 = g_tx2  + r * CC;
#pragma unroll 4
        for (int c = 0; c < CC; c++) {
            acc += x0[c] * sW[c * CC + o];
            acc += x1[c] * sW[CC * CC + c * CC + o];
            acc += x2[c] * sW[2 * CC * CC + c * CC + o];
        }
        out[r * CC + o] = acc;
    }
}

extern "C" void kernel_launch(void* const* d_in, const int* in_sizes, int n_in,
                              void* d_out, int out_size) {
    const float* x        = (const float*)d_in[0];
    const int*   ei       = (const int*)d_in[1];
    const float* ew       = (const float*)d_in[2];
    const float* W        = (const float*)d_in[3];
    const float* adaptive = (const float*)d_in[4];
    const float* bias     = (const float*)d_in[5];
    float* out = (float*)d_out;

    float* tx1; cudaGetSymbolAddress((void**)&tx1, g_tx1);
    float* tx2; cudaGetSymbolAddress((void**)&tx2, g_tx2);

    k_init<<<(NN + 255) / 256, 256>>>(adaptive);
    k_pass1<<<EE / 256, 256>>>(ei);
    k_pass2<<<EE / 256, 256>>>(ei, ew);
    k_scan<<<1, 1024>>>();
    k_pass3<<<EE / 256, 256>>>(ei);

    dim3 sb(64, 4);
    // Tx1 = L @ x
    k_scale<<<(NN * CC) / 256, 256>>>(x);
    k_spmm<<<NN / 4, sb>>>(x, x, tx1, 1.0f, 0.0f);
    // Tx2 = 2 * (L @ Tx1) - x
    k_scale<<<(NN * CC) / 256, 256>>>(tx1);
    k_spmm<<<NN / 4, sb>>>(tx1, x, tx2, 2.0f, -1.0f);
    // out = x@W0 + Tx1@W1 + Tx2@W2 + bias
    k_gemm<<<NN / 32, dim3(64, 4)>>>(x, W, bias, out);
}